// round 1
// baseline (speedup 1.0000x reference)
#include <cuda_runtime.h>
#include <cstdint>

// Problem constants (from reference): N_UNARY=128, NB=64 -> 320 floats per delta row = 80 float4.
// d_out layout: [ out : N*128 fp32 ][ b : E*64 fp32 ]

__global__ void zero_out_kernel(float4* __restrict__ out4, long n4) {
    long i = blockIdx.x * (long)blockDim.x + threadIdx.x;
    if (i < n4) out4[i] = make_float4(0.f, 0.f, 0.f, 0.f);
}

__device__ __forceinline__ void red_add_v4(float* p, float4 v) {
    asm volatile("red.global.add.v4.f32 [%0], {%1, %2, %3, %4};"
                 :: "l"(p), "f"(v.x), "f"(v.y), "f"(v.z), "f"(v.w)
                 : "memory");
}

__global__ void scatter_kernel(const float4* __restrict__ deltas4,  // E * 80 float4
                               const int*    __restrict__ i1,       // E
                               const int*    __restrict__ i2,       // E
                               float*        __restrict__ out,      // N * 128 fp32
                               float4*       __restrict__ bout4,    // E * 16 float4
                               long total)                          // E * 80
{
    long t = blockIdx.x * (long)blockDim.x + threadIdx.x;
    if (t >= total) return;

    long e = t / 80;             // edge id
    int  c = (int)(t - e * 80);  // float4 chunk within the 320-float row

    float4 v = deltas4[t];

    if (c < 32) {
        // ux -> out[i1[e], 4c : 4c+4]
        int row = __ldg(&i1[e]);
        red_add_v4(out + (long)row * 128 + c * 4, v);
    } else if (c < 64) {
        // uy -> out[i2[e], 4(c-32) : ...]
        int row = __ldg(&i2[e]);
        red_add_v4(out + (long)row * 128 + (c - 32) * 4, v);
    } else {
        // b copy: deltas[:, 256:320] -> bout
        bout4[e * 16 + (c - 64)] = v;
    }
}

extern "C" void kernel_launch(void* const* d_in, const int* in_sizes, int n_in,
                              void* d_out, int out_size)
{
    // metadata order: unary(N*128 f32), binary(E*64 f32), deltas(E*320 f32),
    //                 index1(E i32), index2(E i32)
    const long N = in_sizes[0] / 128;
    const long E = in_sizes[2] / 320;

    const float4* deltas4 = (const float4*)d_in[2];
    const int*    i1      = (const int*)d_in[3];
    const int*    i2      = (const int*)d_in[4];

    float*  out   = (float*)d_out;                  // N*128
    float4* bout4 = (float4*)((float*)d_out + N * 128);  // E*64 fp32 = E*16 float4

    // 1) zero the scatter target (b region is fully overwritten; no need to zero)
    {
        long n4 = (N * 128) / 4;
        int  threads = 256;
        long blocks = (n4 + threads - 1) / threads;
        zero_out_kernel<<<(unsigned)blocks, threads>>>((float4*)out, n4);
    }

    // 2) scatter-add + b copy
    {
        long total = E * 80;
        int  threads = 256;
        long blocks = (total + threads - 1) / threads;
        scatter_kernel<<<(unsigned)blocks, threads>>>(deltas4, i1, i2, out, bout4, total);
    }
}

// round 3
// speedup vs baseline: 1.1756x; 1.1756x over previous
#include <cuda_runtime.h>
#include <cstdint>

// Problem: out[N=100000,128] = zeros; out[i1]+=deltas[:,:128]; out[i2]+=deltas[:,128:256];
//          b = deltas[:,256:320].  d_out layout: [ out : N*128 fp32 ][ b : E*64 fp32 ]
//
// L2 policy: out (51.2 MB) should stay resident in the 126 MB L2 so the red RMWs
// hit L2 instead of cycling through DRAM. deltas (640 MB stream) gets evict_first
// via the cache_hint (policy-register) form, since the compact modifier form is
// width-restricted on this ptxas.

__device__ __forceinline__ uint64_t make_evict_last_policy() {
    uint64_t pol;
    asm("createpolicy.fractional.L2::evict_last.b64 %0, 1.0;" : "=l"(pol));
    return pol;
}

__device__ __forceinline__ uint64_t make_evict_first_policy() {
    uint64_t pol;
    asm("createpolicy.fractional.L2::evict_first.b64 %0, 1.0;" : "=l"(pol));
    return pol;
}

__global__ void zero_out_kernel(float4* __restrict__ out4, long n4) {
    long i = blockIdx.x * (long)blockDim.x + threadIdx.x;
    if (i < n4) {
        uint64_t pol = make_evict_last_policy();
        // Prime L2 with the out region marked evict_last.
        asm volatile("st.global.L2::cache_hint.v4.f32 [%0], {%1,%2,%3,%4}, %5;"
                     :: "l"(out4 + i), "f"(0.f), "f"(0.f), "f"(0.f), "f"(0.f), "l"(pol)
                     : "memory");
    }
}

__device__ __forceinline__ float4 ldg_stream(const float4* p, uint64_t pol) {
    float4 v;
    asm("ld.global.nc.L2::cache_hint.v4.f32 {%0,%1,%2,%3}, [%4], %5;"
        : "=f"(v.x), "=f"(v.y), "=f"(v.z), "=f"(v.w) : "l"(p), "l"(pol));
    return v;
}

__device__ __forceinline__ void red_add_v4_el(float* p, float4 v, uint64_t pol) {
    asm volatile("red.global.add.L2::cache_hint.v4.f32 [%0], {%1,%2,%3,%4}, %5;"
                 :: "l"(p), "f"(v.x), "f"(v.y), "f"(v.z), "f"(v.w), "l"(pol)
                 : "memory");
}

__device__ __forceinline__ void stg_stream(float4* p, float4 v) {
    asm volatile("st.global.cs.v4.f32 [%0], {%1,%2,%3,%4};"
                 :: "l"(p), "f"(v.x), "f"(v.y), "f"(v.z), "f"(v.w)
                 : "memory");
}

__global__ void scatter_kernel(const float4* __restrict__ deltas4,  // E * 80 float4
                               const int*    __restrict__ i1,       // E
                               const int*    __restrict__ i2,       // E
                               float*        __restrict__ out,      // N * 128 fp32
                               float4*       __restrict__ bout4,    // E * 16 float4
                               long total)                          // E * 80
{
    long t = blockIdx.x * (long)blockDim.x + threadIdx.x;
    if (t >= total) return;

    long e = t / 80;             // edge id
    int  c = (int)(t - e * 80);  // float4 chunk within the 320-float row

    uint64_t pol_ef = make_evict_first_policy();
    float4 v = ldg_stream(deltas4 + t, pol_ef);

    if (c < 64) {
        uint64_t pol_el = make_evict_last_policy();
        int row;
        int col;
        if (c < 32) { row = __ldg(&i1[e]); col = c; }
        else        { row = __ldg(&i2[e]); col = c - 32; }
        red_add_v4_el(out + (long)row * 128 + col * 4, v, pol_el);
    } else {
        // b copy: deltas[:, 256:320] -> bout (pure stream, don't pollute L2)
        stg_stream(bout4 + e * 16 + (c - 64), v);
    }
}

extern "C" void kernel_launch(void* const* d_in, const int* in_sizes, int n_in,
                              void* d_out, int out_size)
{
    // metadata order: unary(N*128 f32), binary(E*64 f32), deltas(E*320 f32),
    //                 index1(E i32), index2(E i32)
    const long N = in_sizes[0] / 128;
    const long E = in_sizes[2] / 320;

    const float4* deltas4 = (const float4*)d_in[2];
    const int*    i1      = (const int*)d_in[3];
    const int*    i2      = (const int*)d_in[4];

    float*  out   = (float*)d_out;                       // N*128
    float4* bout4 = (float4*)((float*)d_out + N * 128);  // E*16 float4

    // 1) zero the scatter target and pin it in L2 (evict_last)
    {
        long n4 = (N * 128) / 4;
        int  threads = 256;
        long blocks = (n4 + threads - 1) / threads;
        zero_out_kernel<<<(unsigned)blocks, threads>>>((float4*)out, n4);
    }

    // 2) scatter-add + b copy
    {
        long total = E * 80;
        int  threads = 256;
        long blocks = (total + threads - 1) / threads;
        scatter_kernel<<<(unsigned)blocks, threads>>>(deltas4, i1, i2, out, bout4, total);
    }
}

// round 4
// speedup vs baseline: 1.2684x; 1.0790x over previous
#include <cuda_runtime.h>
#include <cstdint>

// Problem: out[N=100000,128] = zeros; out[i1]+=deltas[:,:128]; out[i2]+=deltas[:,128:256];
//          b = deltas[:,256:320].  d_out layout: [ out : N*128 fp32 ][ b : E*64 fp32 ]
//
// R3 strategy: replace 32M red.v4 lane-ops (REDG costs ~1.29 cyc/LANE at the LSU,
// ~150us floor) with 1M cp.reduce.async.bulk ops (512B each) executed by the TMA
// engine. One warp per edge: stage ux||uy (1024B) in SMEM, bulk-reduce both halves
// into the L2-resident out region (evict_last), stream b directly with st.cs.

#define WARPS_PER_BLOCK 8
#define THREADS_PER_BLOCK (WARPS_PER_BLOCK * 32)

__device__ __forceinline__ uint64_t make_evict_last_policy() {
    uint64_t pol;
    asm("createpolicy.fractional.L2::evict_last.b64 %0, 1.0;" : "=l"(pol));
    return pol;
}

__device__ __forceinline__ uint64_t make_evict_first_policy() {
    uint64_t pol;
    asm("createpolicy.fractional.L2::evict_first.b64 %0, 1.0;" : "=l"(pol));
    return pol;
}

__global__ void zero_out_kernel(float4* __restrict__ out4, long n4) {
    long i = blockIdx.x * (long)blockDim.x + threadIdx.x;
    if (i < n4) {
        uint64_t pol = make_evict_last_policy();
        asm volatile("st.global.L2::cache_hint.v4.f32 [%0], {%1,%2,%3,%4}, %5;"
                     :: "l"(out4 + i), "f"(0.f), "f"(0.f), "f"(0.f), "f"(0.f), "l"(pol)
                     : "memory");
    }
}

__device__ __forceinline__ float4 ldg_stream(const float4* p, uint64_t pol) {
    float4 v;
    asm("ld.global.nc.L2::cache_hint.v4.f32 {%0,%1,%2,%3}, [%4], %5;"
        : "=f"(v.x), "=f"(v.y), "=f"(v.z), "=f"(v.w) : "l"(p), "l"(pol));
    return v;
}

__device__ __forceinline__ void stg_stream(float4* p, float4 v) {
    asm volatile("st.global.cs.v4.f32 [%0], {%1,%2,%3,%4};"
                 :: "l"(p), "f"(v.x), "f"(v.y), "f"(v.z), "f"(v.w)
                 : "memory");
}

__device__ __forceinline__ void bulk_reduce_add_f32(float* gdst, uint32_t ssrc,
                                                    uint32_t bytes, uint64_t pol) {
    asm volatile(
        "cp.reduce.async.bulk.global.shared::cta.bulk_group.L2::cache_hint.add.f32 "
        "[%0], [%1], %2, %3;"
        :: "l"(gdst), "r"(ssrc), "r"(bytes), "l"(pol)
        : "memory");
}

__global__ void __launch_bounds__(THREADS_PER_BLOCK)
scatter_kernel(const float4* __restrict__ deltas4,  // E * 80 float4
               const int*    __restrict__ i1,       // E
               const int*    __restrict__ i2,       // E
               float*        __restrict__ out,      // N * 128 fp32
               float4*       __restrict__ bout4,    // E * 16 float4
               long E, long nwarps)
{
    // Per-warp double buffer: 64 float4 = 1024 B (ux 512B || uy 512B)
    __shared__ __align__(16) float4 buf[WARPS_PER_BLOCK][2][64];

    const int wid  = threadIdx.x >> 5;
    const int lane = threadIdx.x & 31;
    const long gw  = (long)blockIdx.x * WARPS_PER_BLOCK + wid;

    const uint64_t pol_ef = make_evict_first_policy();
    const uint64_t pol_el = make_evict_last_policy();

    int parity = 0;
    for (long e = gw; e < E; e += nwarps, parity ^= 1) {
        // Buffer[parity] was last handed to the TMA engine 2 iterations ago;
        // wait until at most 1 group still has an unread source.
        if (lane == 0)
            asm volatile("cp.async.bulk.wait_group.read 1;" ::: "memory");
        __syncwarp();

        const float4* row = deltas4 + e * 80;

        // ux: chunks [0,32) ; uy: chunks [32,64) -> SMEM (coalesced)
        float4 v0 = ldg_stream(row + lane,      pol_ef);
        float4 v1 = ldg_stream(row + 32 + lane, pol_ef);
        buf[wid][parity][lane]      = v0;
        buf[wid][parity][32 + lane] = v1;

        // b: chunks [64,80) -> straight to output, bypass SMEM
        if (lane < 16) {
            float4 vb = ldg_stream(row + 64 + lane, pol_ef);
            stg_stream(bout4 + e * 16 + lane, vb);
        }
        __syncwarp();

        if (lane == 0) {
            asm volatile("fence.proxy.async.shared::cta;" ::: "memory");
            int r1 = __ldg(&i1[e]);
            int r2 = __ldg(&i2[e]);
            uint32_t s = (uint32_t)__cvta_generic_to_shared(&buf[wid][parity][0]);
            bulk_reduce_add_f32(out + (long)r1 * 128, s,       512, pol_el);
            bulk_reduce_add_f32(out + (long)r2 * 128, s + 512, 512, pol_el);
            asm volatile("cp.async.bulk.commit_group;" ::: "memory");
        }
    }

    // Drain all pending bulk groups before exit.
    if (lane == 0)
        asm volatile("cp.async.bulk.wait_group 0;" ::: "memory");
}

extern "C" void kernel_launch(void* const* d_in, const int* in_sizes, int n_in,
                              void* d_out, int out_size)
{
    // metadata order: unary(N*128 f32), binary(E*64 f32), deltas(E*320 f32),
    //                 index1(E i32), index2(E i32)
    const long N = in_sizes[0] / 128;
    const long E = in_sizes[2] / 320;

    const float4* deltas4 = (const float4*)d_in[2];
    const int*    i1      = (const int*)d_in[3];
    const int*    i2      = (const int*)d_in[4];

    float*  out   = (float*)d_out;                       // N*128
    float4* bout4 = (float4*)((float*)d_out + N * 128);  // E*16 float4

    // 1) zero the scatter target and pin it in L2 (evict_last)
    {
        long n4 = (N * 128) / 4;
        int  threads = 256;
        long blocks = (n4 + threads - 1) / threads;
        zero_out_kernel<<<(unsigned)blocks, threads>>>((float4*)out, n4);
    }

    // 2) scatter-add (TMA bulk-reduce) + b copy
    {
        int  blocks = 2048;                       // 16384 warps, ~30 edges each
        long nwarps = (long)blocks * WARPS_PER_BLOCK;
        scatter_kernel<<<blocks, THREADS_PER_BLOCK>>>(deltas4, i1, i2, out, bout4, E, nwarps);
    }
}